// round 1
// baseline (speedup 1.0000x reference)
#include <cuda_runtime.h>

// Problem constants (from reference):
//   B=64, N=8192, C=80, M=300, S=B*M=19200
// Inputs (metadata order):
//   d_in[0] pred_boxes       float32 (B, N, 4)      = 2,097,152
//   d_in[1] pred_scores      float32 (B, N, C)      = 41,943,040
//   d_in[2] selected_indexes int32   (S, 3)         = 57,600
// Output (concatenated, float32, total 115,264):
//   [0      ..     64) num_predictions (B,1)   (int -> float)
//   [64     ..  76864) det_boxes       (B,M,4)
//   [76864  ..  96064) det_scores      (B,M)
//   [96064  .. 115264) det_classes     (B,M)   (int -> float)

#define B_   64
#define N_   8192
#define C_   80
#define M_   300
#define S_   19200

#define OFF_BOXES   64
#define OFF_SCORES  76864
#define OFF_CLASSES 96064

#define NWARP 8
#define SEG   (S_ / NWARP)   // 2400, exact multiple of 32

__global__ __launch_bounds__(NWARP * 32, 1)
void picknms_kernel(const float* __restrict__ pred_boxes,
                    const float* __restrict__ pred_scores,
                    const int*   __restrict__ sel,
                    float*       __restrict__ out)
{
    const int b    = blockIdx.x;          // one block per batch
    const int tid  = threadIdx.x;
    const int wid  = tid >> 5;
    const int lane = tid & 31;

    // ---- Phase 0: zero this batch's output regions ----
    {
        float* ob = out + OFF_BOXES + b * (M_ * 4);
        for (int i = tid; i < M_ * 4; i += NWARP * 32) ob[i] = 0.0f;
        float* os = out + OFF_SCORES + b * M_;
        float* oc = out + OFF_CLASSES + b * M_;
        for (int i = tid; i < M_; i += NWARP * 32) { os[i] = 0.0f; oc[i] = 0.0f; }
    }

    // ---- Phase 1: each warp counts matches in its contiguous segment ----
    __shared__ int warp_cnt[NWARP];
    const int seg_lo = wid * SEG;
    const int seg_hi = seg_lo + SEG;

    int cnt = 0;
    #pragma unroll 4
    for (int i = seg_lo + lane; i < seg_hi; i += 32) {
        int bi = __ldg(&sel[3 * i]);
        unsigned m = __ballot_sync(0xffffffffu, bi == b);
        cnt += __popc(m);
    }
    if (lane == 0) warp_cnt[wid] = cnt;
    __syncthreads();   // also orders Phase-0 zeroing before Phase-2 scatter

    // exclusive prefix over the 8 warp counts (every thread computes it)
    int base = 0, total = 0;
    #pragma unroll
    for (int w = 0; w < NWARP; w++) {
        int c = warp_cnt[w];
        if (w < wid) base += c;
        total += c;
    }
    if (tid == 0) out[b] = (float)total;   // num_predictions (unclamped count)

    // ---- Phase 2: re-scan, compute exact ranks, gather + scatter rows ----
    int run = base;
    for (int i = seg_lo + lane; i < seg_hi; i += 32) {
        int bi = __ldg(&sel[3 * i]);
        unsigned m = __ballot_sync(0xffffffffu, bi == b);
        if (bi == b) {
            int r = run + __popc(m & ((1u << lane) - 1u));
            if (r < M_) {
                int lab = __ldg(&sel[3 * i + 1]);
                int box = __ldg(&sel[3 * i + 2]);
                const float4 bx =
                    *reinterpret_cast<const float4*>(pred_boxes + ((size_t)b * N_ + box) * 4);
                float sc = __ldg(&pred_scores[(b * N_ + box) * C_ + lab]);
                *reinterpret_cast<float4*>(out + OFF_BOXES + b * (M_ * 4) + r * 4) = bx;
                out[OFF_SCORES  + b * M_ + r] = sc;
                out[OFF_CLASSES + b * M_ + r] = (float)lab;
            }
        }
        run += __popc(m);
    }
}

extern "C" void kernel_launch(void* const* d_in, const int* in_sizes, int n_in,
                              void* d_out, int out_size)
{
    const float* pred_boxes  = (const float*)d_in[0];
    const float* pred_scores = (const float*)d_in[1];
    const int*   sel         = (const int*)d_in[2];
    float*       out         = (float*)d_out;

    picknms_kernel<<<B_, NWARP * 32>>>(pred_boxes, pred_scores, sel, out);
}

// round 4
// speedup vs baseline: 2.8915x; 2.8915x over previous
#include <cuda_runtime.h>

// Problem constants:
//   B=64, N=8192, C=80, M=300, S=B*M=19200
// Inputs:
//   d_in[0] pred_boxes       float32 (B, N, 4)
//   d_in[1] pred_scores      float32 (B, N, C)
//   d_in[2] selected_indexes int32   (S, 3)  rows = (b, label, box)
// Output (concatenated float32, 115264 elems):
//   [0      ..     64) num_predictions (B,1)  (int -> float)
//   [64     ..  76864) det_boxes       (B,M,4)
//   [76864  ..  96064) det_scores      (B,M)
//   [96064  .. 115264) det_classes    (B,M)   (int -> float)

#define B_   64
#define N_   8192
#define C_   80
#define M_   300
#define S_   19200

#define OFF_BOXES   64
#define OFF_SCORES  76864
#define OFF_CLASSES 96064

#define NWARP 8
#define NTHR  (NWARP * 32)
#define SEG   (S_ / NWARP)      // 2400, exact multiple of 32
#define ITERS (SEG / 32)        // 75

__global__ __launch_bounds__(NTHR, 1)
void picknms_kernel(const float* __restrict__ pred_boxes,
                    const float* __restrict__ pred_scores,
                    const int*   __restrict__ sel,
                    float*       __restrict__ out)
{
    const int b    = blockIdx.x;          // one block per batch
    const int tid  = threadIdx.x;
    const int wid  = tid >> 5;
    const int lane = tid & 31;
    const unsigned lt_mask = (1u << lane) - 1u;

    __shared__ int lists[NWARP][M_];      // packed (lab<<13)|box per local rank
    __shared__ int warp_cnt[NWARP];

    // ---- Single scan: count + compact matches (local rank < M only) ----
    const int seg_lo = wid * SEG;
    int cnt = 0;
    #pragma unroll 8
    for (int k = 0; k < ITERS; k++) {
        const int i   = seg_lo + lane + k * 32;
        // issue all three loads up-front (same sector, one round trip)
        const int bi  = sel[3 * i];
        const int lab = sel[3 * i + 1];
        const int box = sel[3 * i + 2];
        const unsigned m = __ballot_sync(0xffffffffu, bi == b);
        if (bi == b) {
            const int j = cnt + __popc(m & lt_mask);
            if (j < M_) lists[wid][j] = ((lab & 0x7f) << 13) | (box & (N_ - 1));
        }
        cnt += __popc(m);
    }
    if (lane == 0) warp_cnt[wid] = cnt;
    __syncthreads();

    // ---- Per-warp exclusive prefix (every thread computes the same) ----
    int pre[NWARP + 1];
    pre[0] = 0;
    #pragma unroll
    for (int w = 0; w < NWARP; w++) pre[w + 1] = pre[w] + warp_cnt[w];
    const int total = pre[NWARP];
    if (tid == 0) out[b] = (float)total;          // unclamped count
    const int used = total < M_ ? total : M_;

    // ---- Epilogue: all 256 threads process ranks [0, M) ----
    float* ob = out + OFF_BOXES   + b * (M_ * 4);
    float* os = out + OFF_SCORES  + b * M_;
    float* oc = out + OFF_CLASSES + b * M_;

    for (int r = tid; r < M_; r += NTHR) {        // r = tid, tid+256
        if (r < used) {
            // locate owning warp (branchless 8-step)
            int w = 0;
            #pragma unroll
            for (int ww = 1; ww < NWARP; ww++) w += (r >= pre[ww]);
            const int packed = lists[w][r - pre[w]];
            const int lab = (packed >> 13) & 0x7f;
            const int box = packed & (N_ - 1);
            const float4 bx =
                *reinterpret_cast<const float4*>(pred_boxes + ((size_t)(b * N_ + box)) * 4);
            const float sc = pred_scores[((size_t)(b * N_ + box)) * C_ + lab];
            *reinterpret_cast<float4*>(ob + r * 4) = bx;
            os[r] = sc;
            oc[r] = (float)lab;
        } else {
            *reinterpret_cast<float4*>(ob + r * 4) = make_float4(0.f, 0.f, 0.f, 0.f);
            os[r] = 0.0f;
            oc[r] = 0.0f;
        }
    }
}

extern "C" void kernel_launch(void* const* d_in, const int* in_sizes, int n_in,
                              void* d_out, int out_size)
{
    const float* pred_boxes  = (const float*)d_in[0];
    const float* pred_scores = (const float*)d_in[1];
    const int*   sel         = (const int*)d_in[2];
    float*       out         = (float*)d_out;

    picknms_kernel<<<B_, NTHR>>>(pred_boxes, pred_scores, sel, out);
}

// round 6
// speedup vs baseline: 4.0252x; 1.3921x over previous
#include <cuda_runtime.h>

// Problem constants:
//   B=64, N=8192, C=80, M=300, S=B*M=19200
// Inputs:
//   d_in[0] pred_boxes       float32 (B, N, 4)
//   d_in[1] pred_scores      float32 (B, N, C)
//   d_in[2] selected_indexes int32   (S, 3)  rows = (b, label, box)
// Output (concatenated float32, 115264 elems):
//   [0      ..     64) num_predictions (B,1)  (int -> float)
//   [64     ..  76864) det_boxes       (B,M,4)
//   [76864  ..  96064) det_scores      (B,M)
//   [96064  .. 115264) det_classes    (B,M)   (int -> float)

#define B_   64
#define N_   8192
#define C_   80
#define M_   300
#define S_   19200

#define OFF_BOXES   64
#define OFF_SCORES  76864
#define OFF_CLASSES 96064

#define NWARP 24
#define NTHR  (NWARP * 32)      // 768
#define SEG   (S_ / NWARP)      // 800
#define ITERS (SEG / 32)        // 25

__global__ __launch_bounds__(NTHR, 1)
void picknms_kernel(const float* __restrict__ pred_boxes,
                    const float* __restrict__ pred_scores,
                    const int*   __restrict__ sel,
                    float*       __restrict__ out)
{
    const int b    = blockIdx.x;          // one block per batch
    const int tid  = threadIdx.x;
    const int wid  = tid >> 5;
    const int lane = tid & 31;
    const unsigned lt_mask = (1u << lane) - 1u;

    __shared__ int lists[NWARP][M_];      // packed (lab<<13)|box per local rank
    __shared__ int warp_cnt[NWARP];
    __shared__ int warp_pre[NWARP + 1];   // exclusive prefix

    // ---- Single scan: count + compact matches (local rank < M only) ----
    // Only the batch field is loaded unconditionally; lab/box load on match
    // (same 12B region -> L1 hit).
    const int seg_lo = wid * SEG;
    int cnt = 0;
    #pragma unroll
    for (int k = 0; k < ITERS; k++) {
        const int i  = seg_lo + lane + k * 32;
        const int bi = sel[3 * i];
        const unsigned m = __ballot_sync(0xffffffffu, bi == b);
        if (bi == b) {
            const int j = cnt + __popc(m & lt_mask);
            if (j < M_) {
                const int lab = sel[3 * i + 1];
                const int box = sel[3 * i + 2];
                lists[wid][j] = ((lab & 0x7f) << 13) | (box & (N_ - 1));
            }
        }
        cnt += __popc(m);
    }
    if (lane == 0) warp_cnt[wid] = cnt;
    __syncthreads();

    // ---- Exclusive prefix over warp counts (thread 0, trivial) ----
    if (tid == 0) {
        int acc = 0;
        #pragma unroll
        for (int w = 0; w < NWARP; w++) { warp_pre[w] = acc; acc += warp_cnt[w]; }
        warp_pre[NWARP] = acc;
        out[b] = (float)acc;              // unclamped count
    }
    __syncthreads();

    const int total = warp_pre[NWARP];
    const int used  = total < M_ ? total : M_;

    // ---- Epilogue: threads cover ranks [0, M) in one pass (NTHR > M) ----
    float* ob = out + OFF_BOXES   + b * (M_ * 4);
    float* os = out + OFF_SCORES  + b * M_;
    float* oc = out + OFF_CLASSES + b * M_;

    const int r = tid;
    if (r < M_) {
        if (r < used) {
            // locate owning warp via smem prefix
            int w = 0;
            #pragma unroll
            for (int ww = 1; ww < NWARP; ww++) w += (r >= warp_pre[ww]);
            const int packed = lists[w][r - warp_pre[w]];
            const int lab = (packed >> 13) & 0x7f;
            const int box = packed & (N_ - 1);
            const float4 bx =
                *reinterpret_cast<const float4*>(pred_boxes + ((size_t)(b * N_ + box)) * 4);
            const float sc = pred_scores[((size_t)(b * N_ + box)) * C_ + lab];
            *reinterpret_cast<float4*>(ob + r * 4) = bx;
            os[r] = sc;
            oc[r] = (float)lab;
        } else {
            *reinterpret_cast<float4*>(ob + r * 4) = make_float4(0.f, 0.f, 0.f, 0.f);
            os[r] = 0.0f;
            oc[r] = 0.0f;
        }
    }
}

extern "C" void kernel_launch(void* const* d_in, const int* in_sizes, int n_in,
                              void* d_out, int out_size)
{
    const float* pred_boxes  = (const float*)d_in[0];
    const float* pred_scores = (const float*)d_in[1];
    const int*   sel         = (const int*)d_in[2];
    float*       out         = (float*)d_out;

    picknms_kernel<<<B_, NTHR>>>(pred_boxes, pred_scores, sel, out);
}